// round 10
// baseline (speedup 1.0000x reference)
#include <cuda_runtime.h>
#include <cuda_bf16.h>
#include <math_constants.h>
#include <cstdint>

#define N_ROWS 2048
#define DIM    1024
#define VOC    32000
#define KNN    32

// ---------------- scratch (static device globals: allocation-free) ----------
__device__ __nv_bfloat16 g_featb[(size_t)N_ROWS * 2048]; // [N, 2D] bf16
__device__ __nv_bfloat16 g_wb[(size_t)DIM * 2048];       // mw_w1 bf16
__device__ float g_knnw[N_ROWS * KNN];                   // softmax(-d/bw)
__device__ float g_mixp[N_ROWS];                         // partial mhid.w2 dots

// ---------------- k0: convert mw_w1 to bf16 + zero mixing partials ----------
__global__ void k0_convert_w(const float* __restrict__ w1) {
    int idx = blockIdx.x * blockDim.x + threadIdx.x;     // exactly DIM*2048
    g_wb[idx] = __float2bfloat16(w1[idx]);
    if (idx < N_ROWS) g_mixp[idx] = 0.f;
}

// ---------------- k1: ctx mean + feat(bf16) + bandwidth + knn softmax -------
__global__ __launch_bounds__(256) void k1_ctx(const float* __restrict__ hidden,
                       const float* __restrict__ sh,
                       const float* __restrict__ dist,
                       const float* __restrict__ bw_w,
                       const float* __restrict__ bw_b) {
    int n = blockIdx.x;
    int tid = threadIdx.x;                               // 256 threads
    int d = tid * 4;                                     // each thread: 4 dims
    const float* shrow = sh + (size_t)n * KNN * DIM;
    const float* hrow  = hidden + (size_t)n * DIM;

    float4 acc = make_float4(0.f, 0.f, 0.f, 0.f);
    #pragma unroll
    for (int k = 0; k < KNN; k++) {
        float4 v = *(const float4*)(shrow + k * DIM + d);
        acc.x += v.x; acc.y += v.y; acc.z += v.z; acc.w += v.w;
    }
    const float inv = 1.f / 32.f;
    float4 ctx = make_float4(acc.x * inv, acc.y * inv, acc.z * inv, acc.w * inv);
    float4 h = *(const float4*)(hrow + d);

    __nv_bfloat162* fb = (__nv_bfloat162*)&g_featb[(size_t)n * 2048 + d];
    fb[0] = __nv_bfloat162(__float2bfloat16(h.x), __float2bfloat16(h.y));
    fb[1] = __nv_bfloat162(__float2bfloat16(h.z), __float2bfloat16(h.w));
    __nv_bfloat162* fb2 = (__nv_bfloat162*)&g_featb[(size_t)n * 2048 + DIM + d];
    fb2[0] = __nv_bfloat162(__float2bfloat16(ctx.x), __float2bfloat16(ctx.y));
    fb2[1] = __nv_bfloat162(__float2bfloat16(ctx.z), __float2bfloat16(ctx.w));

    float4 w0 = *(const float4*)(bw_w + d);
    float4 w1 = *(const float4*)(bw_w + DIM + d);
    float bwacc = h.x * w0.x + h.y * w0.y + h.z * w0.z + h.w * w0.w
                + ctx.x * w1.x + ctx.y * w1.y + ctx.z * w1.z + ctx.w * w1.w;

    __shared__ float red[8];
    #pragma unroll
    for (int o = 16; o > 0; o >>= 1) bwacc += __shfl_xor_sync(0xffffffffu, bwacc, o);
    if ((tid & 31) == 0) red[tid >> 5] = bwacc;
    __syncthreads();
    __shared__ float s_bw;
    if (tid == 0) {
        float t = 0.f;
        #pragma unroll
        for (int i = 0; i < 8; i++) t += red[i];
        s_bw = expf(t + bw_b[0]);
    }
    __syncthreads();
    if (tid < 32) {
        float bw = s_bw;
        float t = -dist[n * KNN + tid] / bw;
        float m = t;
        #pragma unroll
        for (int o = 16; o > 0; o >>= 1) m = fmaxf(m, __shfl_xor_sync(0xffffffffu, m, o));
        float e = __expf(t - m);
        float ssum = e;
        #pragma unroll
        for (int o = 16; o > 0; o >>= 1) ssum += __shfl_xor_sync(0xffffffffu, ssum, o);
        g_knnw[n * KNN + tid] = e / ssum;
    }
}

// ---------------- k2: bf16 MMA GEMM + fused mixing partial dot --------------
#define BM 128
#define BN 128
#define BK 32
#define SSTR 40

__device__ __forceinline__ void mma16816(float c[4], const uint32_t a[4], const uint32_t b[2]) {
    asm volatile(
        "mma.sync.aligned.m16n8k16.row.col.f32.bf16.bf16.f32 "
        "{%0,%1,%2,%3}, {%4,%5,%6,%7}, {%8,%9}, {%0,%1,%2,%3};\n"
        : "+f"(c[0]), "+f"(c[1]), "+f"(c[2]), "+f"(c[3])
        : "r"(a[0]), "r"(a[1]), "r"(a[2]), "r"(a[3]), "r"(b[0]), "r"(b[1]));
}

__global__ __launch_bounds__(256) void k2_gemm(const float* __restrict__ b1,
                                               const float* __restrict__ w2) {
    __shared__ __nv_bfloat16 As[BM * SSTR];
    __shared__ __nv_bfloat16 Bs[BN * SSTR];
    int tid = threadIdx.x;
    int lane = tid & 31, warp = tid >> 5;
    int wm = warp >> 1, wn = warp & 1;
    int g = lane >> 2, q = lane & 3;
    int bmrow = blockIdx.y * BM;
    int bncol = blockIdx.x * BN;

    float acc[2][8][4];
    #pragma unroll
    for (int i = 0; i < 2; i++)
        #pragma unroll
        for (int j = 0; j < 8; j++)
            #pragma unroll
            for (int c = 0; c < 4; c++) acc[i][j][c] = 0.f;

    int r0 = tid >> 2;
    int cs0 = (tid & 3) * 8;
    const __nv_bfloat16* Ag  = g_featb + (size_t)(bmrow + r0) * 2048 + cs0;
    const __nv_bfloat16* Ag2 = Ag + (size_t)64 * 2048;
    const __nv_bfloat16* Bg  = g_wb   + (size_t)(bncol + r0) * 2048 + cs0;
    const __nv_bfloat16* Bg2 = Bg + (size_t)64 * 2048;

    uint4 pa0 = *(const uint4*)(Ag);
    uint4 pa1 = *(const uint4*)(Ag2);
    uint4 pb0 = *(const uint4*)(Bg);
    uint4 pb1 = *(const uint4*)(Bg2);

    const int KT = 2048 / BK;
    for (int kt = 0; kt < KT; kt++) {
        *(uint4*)&As[r0 * SSTR + cs0]        = pa0;
        *(uint4*)&As[(r0 + 64) * SSTR + cs0] = pa1;
        *(uint4*)&Bs[r0 * SSTR + cs0]        = pb0;
        *(uint4*)&Bs[(r0 + 64) * SSTR + cs0] = pb1;
        __syncthreads();
        if (kt + 1 < KT) {
            int kb = (kt + 1) * BK;
            pa0 = *(const uint4*)(Ag + kb);
            pa1 = *(const uint4*)(Ag2 + kb);
            pb0 = *(const uint4*)(Bg + kb);
            pb1 = *(const uint4*)(Bg2 + kb);
        }
        #pragma unroll
        for (int ks = 0; ks < BK; ks += 16) {
            uint32_t a[2][4], b[8][2];
            #pragma unroll
            for (int mt = 0; mt < 2; mt++) {
                int rr = (wm * 32 + mt * 16 + g) * SSTR + ks + q * 2;
                a[mt][0] = *(const uint32_t*)&As[rr];
                a[mt][1] = *(const uint32_t*)&As[rr + 8 * SSTR];
                a[mt][2] = *(const uint32_t*)&As[rr + 8];
                a[mt][3] = *(const uint32_t*)&As[rr + 8 * SSTR + 8];
            }
            #pragma unroll
            for (int nt = 0; nt < 8; nt++) {
                int rr = (wn * 64 + nt * 8 + g) * SSTR + ks + q * 2;
                b[nt][0] = *(const uint32_t*)&Bs[rr];
                b[nt][1] = *(const uint32_t*)&Bs[rr + 8];
            }
            #pragma unroll
            for (int mt = 0; mt < 2; mt++)
                #pragma unroll
                for (int nt = 0; nt < 8; nt++)
                    mma16816(acc[mt][nt], a[mt], b[nt]);
        }
        __syncthreads();
    }

    #pragma unroll
    for (int mt = 0; mt < 2; mt++) {
        int row = bmrow + wm * 32 + mt * 16 + g;
        float prow = 0.f, prow8 = 0.f;
        #pragma unroll
        for (int nt = 0; nt < 8; nt++) {
            int col = bncol + wn * 64 + nt * 8 + q * 2;
            float bb0 = b1[col], bb1 = b1[col + 1];
            float w20 = w2[col], w21 = w2[col + 1];
            float v0 = fmaxf(acc[mt][nt][0] + bb0, 0.f);
            float v1 = fmaxf(acc[mt][nt][1] + bb1, 0.f);
            float v2 = fmaxf(acc[mt][nt][2] + bb0, 0.f);
            float v3 = fmaxf(acc[mt][nt][3] + bb1, 0.f);
            prow  = fmaf(v0, w20, fmaf(v1, w21, prow));
            prow8 = fmaf(v2, w20, fmaf(v3, w21, prow8));
        }
        prow  += __shfl_xor_sync(0xffffffffu, prow, 1);
        prow  += __shfl_xor_sync(0xffffffffu, prow, 2);
        prow8 += __shfl_xor_sync(0xffffffffu, prow8, 1);
        prow8 += __shfl_xor_sync(0xffffffffu, prow8, 2);
        if (q == 0) {
            atomicAdd(&g_mixp[row], prow);
            atomicAdd(&g_mixp[row + 8], prow8);
        }
    }
}

// ---------------- k4: row-per-CTA, 1 CTA/SM (smem governor), 2 phases -------
// Phase A: sum of exp (proven __ldcg loop). Phase B: re-read (only ~148 rows
// in flight -> 19MB, L2-resident) and out = x + log(coef), __stcs. 1 CTA/SM
// keeps the write stream at ~148 concurrent rows — the regime that measured
// 3.2-3.4 TB/s — without R3's 3x128KB smem sweeps. Patch tail exact fp32.
__global__ __launch_bounds__(1024) void k4_out(const float* __restrict__ logits,
                                               const int* __restrict__ tok,
                                               const float* __restrict__ b2,
                                               float* __restrict__ out) {
    extern __shared__ float smem_gov[];    // ~99KB requested, only [0..34) used
    float* red = smem_gov;                 // 32 warp partials + 2 scalars
    int n = blockIdx.x;
    int tid = threadIdx.x;
    int lane = tid & 31, warp = tid >> 5;
    const float* lrow = logits + (size_t)n * VOC;
    float* orow = out + (size_t)n * VOC;

    // phase A: sum of exp(x) over the row
    float s = 0.f;
    #pragma unroll 8
    for (int i = tid * 4; i < VOC; i += 4096) {
        float4 x = __ldcg((const float4*)(lrow + i));
        s += (__expf(x.x) + __expf(x.y)) + (__expf(x.z) + __expf(x.w));
    }
    #pragma unroll
    for (int o = 16; o > 0; o >>= 1) s += __shfl_xor_sync(0xffffffffu, s, o);
    if (lane == 0) red[warp] = s;
    __syncthreads();
    if (tid == 0) {
        float t = 0.f;
        #pragma unroll
        for (int i = 0; i < 32; i++) t += red[i];
        float mix = 1.f / (1.f + expf(-(g_mixp[n] + b2[0])));
        float coef = (1.f - mix) / t;
        red[32] = logf(coef);   // lc
        red[33] = mix;
        red[34] = coef;
    }
    __syncthreads();
    float lc = red[32];

    // phase B: out = x + log(coef)   (row re-read; L2-resident at 1 CTA/SM)
    #pragma unroll 8
    for (int i = tid * 4; i < VOC; i += 4096) {
        float4 x = __ldcg((const float4*)(lrow + i));
        x.x += lc; x.y += lc; x.z += lc; x.w += lc;
        __stcs((float4*)(orow + i), x);
    }
    __syncthreads();   // order row writes before the patch overwrites

    // patch the <=32 scattered tokens with the exact fp32 formula
    if (tid < KNN) {
        float mix  = red[33];
        float coef = red[34];
        int t = tok[n * KNN + tid];
        float w = g_knnw[n * KNN + tid] * mix;
        unsigned grp = __match_any_sync(0xffffffffu, t);
        float tot = 0.f;
        #pragma unroll
        for (int j = 0; j < 32; j++)
            if (grp & (1u << j)) tot += __shfl_sync(0xffffffffu, w, j);
        if ((grp & ((1u << tid) - 1u)) == 0) {           // lowest lane of group
            float e = __expf(__ldcg(&lrow[t]));
            orow[t] = __logf(fmaf(e, coef, tot + 1e-10f));
        }
    }
}

#define K4_SMEM (99 * 1024)   // occupancy governor: forces 1 CTA/SM

// ---------------- launch -----------------------------------------------------
extern "C" void kernel_launch(void* const* d_in, const int* in_sizes, int n_in,
                              void* d_out, int out_size) {
    const float* hidden = (const float*)d_in[0];
    const float* logits = (const float*)d_in[1];
    const float* dist   = (const float*)d_in[2];
    const int*   tok    = (const int*)d_in[3];
    const float* sh     = (const float*)d_in[4];
    const float* bw_w   = (const float*)d_in[5];
    const float* bw_b   = (const float*)d_in[6];
    const float* mw_w1  = (const float*)d_in[7];
    const float* mw_b1  = (const float*)d_in[8];
    const float* mw_w2  = (const float*)d_in[9];
    const float* mw_b2  = (const float*)d_in[10];
    float* out = (float*)d_out;

    cudaFuncSetAttribute(k4_out, cudaFuncAttributeMaxDynamicSharedMemorySize,
                         K4_SMEM);

    k0_convert_w<<<2048, 1024>>>(mw_w1);
    k1_ctx<<<N_ROWS, 256>>>(hidden, sh, dist, bw_w, bw_b);
    dim3 g2(DIM / BN, N_ROWS / BM);   // (8, 16)
    k2_gemm<<<g2, 256>>>(mw_b1, mw_w2);
    k4_out<<<N_ROWS, 1024, K4_SMEM>>>(logits, tok, mw_b2, out);
}

// round 11
// speedup vs baseline: 1.2528x; 1.2528x over previous
#include <cuda_runtime.h>
#include <cuda_bf16.h>
#include <cuda_fp16.h>
#include <math_constants.h>
#include <cstdint>

#define N_ROWS 2048
#define DIM    1024
#define VOC    32000
#define KNN    32

// ---------------- scratch (static device globals: allocation-free) ----------
__device__ __nv_bfloat16 g_featb[(size_t)N_ROWS * 2048]; // [N, 2D] bf16
__device__ __nv_bfloat16 g_wb[(size_t)DIM * 2048];       // mw_w1 bf16
__device__ float g_knnw[N_ROWS * KNN];                   // softmax(-d/bw)
__device__ float g_mixp[N_ROWS];                         // partial mhid.w2 dots

// ---------------- k0: convert mw_w1 to bf16 + zero mixing partials ----------
__global__ void k0_convert_w(const float* __restrict__ w1) {
    int idx = blockIdx.x * blockDim.x + threadIdx.x;     // exactly DIM*2048
    g_wb[idx] = __float2bfloat16(w1[idx]);
    if (idx < N_ROWS) g_mixp[idx] = 0.f;
}

// ---------------- k1: ctx mean + feat(bf16) + bandwidth + knn softmax -------
__global__ __launch_bounds__(256) void k1_ctx(const float* __restrict__ hidden,
                       const float* __restrict__ sh,
                       const float* __restrict__ dist,
                       const float* __restrict__ bw_w,
                       const float* __restrict__ bw_b) {
    int n = blockIdx.x;
    int tid = threadIdx.x;                               // 256 threads
    int d = tid * 4;                                     // each thread: 4 dims
    const float* shrow = sh + (size_t)n * KNN * DIM;
    const float* hrow  = hidden + (size_t)n * DIM;

    float4 acc = make_float4(0.f, 0.f, 0.f, 0.f);
    #pragma unroll
    for (int k = 0; k < KNN; k++) {
        float4 v = *(const float4*)(shrow + k * DIM + d);
        acc.x += v.x; acc.y += v.y; acc.z += v.z; acc.w += v.w;
    }
    const float inv = 1.f / 32.f;
    float4 ctx = make_float4(acc.x * inv, acc.y * inv, acc.z * inv, acc.w * inv);
    float4 h = *(const float4*)(hrow + d);

    __nv_bfloat162* fb = (__nv_bfloat162*)&g_featb[(size_t)n * 2048 + d];
    fb[0] = __nv_bfloat162(__float2bfloat16(h.x), __float2bfloat16(h.y));
    fb[1] = __nv_bfloat162(__float2bfloat16(h.z), __float2bfloat16(h.w));
    __nv_bfloat162* fb2 = (__nv_bfloat162*)&g_featb[(size_t)n * 2048 + DIM + d];
    fb2[0] = __nv_bfloat162(__float2bfloat16(ctx.x), __float2bfloat16(ctx.y));
    fb2[1] = __nv_bfloat162(__float2bfloat16(ctx.z), __float2bfloat16(ctx.w));

    float4 w0 = *(const float4*)(bw_w + d);
    float4 w1 = *(const float4*)(bw_w + DIM + d);
    float bwacc = h.x * w0.x + h.y * w0.y + h.z * w0.z + h.w * w0.w
                + ctx.x * w1.x + ctx.y * w1.y + ctx.z * w1.z + ctx.w * w1.w;

    __shared__ float red[8];
    #pragma unroll
    for (int o = 16; o > 0; o >>= 1) bwacc += __shfl_xor_sync(0xffffffffu, bwacc, o);
    if ((tid & 31) == 0) red[tid >> 5] = bwacc;
    __syncthreads();
    __shared__ float s_bw;
    if (tid == 0) {
        float t = 0.f;
        #pragma unroll
        for (int i = 0; i < 8; i++) t += red[i];
        s_bw = expf(t + bw_b[0]);
    }
    __syncthreads();
    if (tid < 32) {
        float bw = s_bw;
        float t = -dist[n * KNN + tid] / bw;
        float m = t;
        #pragma unroll
        for (int o = 16; o > 0; o >>= 1) m = fmaxf(m, __shfl_xor_sync(0xffffffffu, m, o));
        float e = __expf(t - m);
        float ssum = e;
        #pragma unroll
        for (int o = 16; o > 0; o >>= 1) ssum += __shfl_xor_sync(0xffffffffu, ssum, o);
        g_knnw[n * KNN + tid] = e / ssum;
    }
}

// ---------------- k2: bf16 MMA GEMM + fused mixing partial dot --------------
#define BM 128
#define BN 128
#define BK 32
#define SSTR 40

__device__ __forceinline__ void mma16816(float c[4], const uint32_t a[4], const uint32_t b[2]) {
    asm volatile(
        "mma.sync.aligned.m16n8k16.row.col.f32.bf16.bf16.f32 "
        "{%0,%1,%2,%3}, {%4,%5,%6,%7}, {%8,%9}, {%0,%1,%2,%3};\n"
        : "+f"(c[0]), "+f"(c[1]), "+f"(c[2]), "+f"(c[3])
        : "r"(a[0]), "r"(a[1]), "r"(a[2]), "r"(a[3]), "r"(b[0]), "r"(b[1]));
}

__global__ __launch_bounds__(256) void k2_gemm(const float* __restrict__ b1,
                                               const float* __restrict__ w2) {
    __shared__ __nv_bfloat16 As[BM * SSTR];
    __shared__ __nv_bfloat16 Bs[BN * SSTR];
    int tid = threadIdx.x;
    int lane = tid & 31, warp = tid >> 5;
    int wm = warp >> 1, wn = warp & 1;
    int g = lane >> 2, q = lane & 3;
    int bmrow = blockIdx.y * BM;
    int bncol = blockIdx.x * BN;

    float acc[2][8][4];
    #pragma unroll
    for (int i = 0; i < 2; i++)
        #pragma unroll
        for (int j = 0; j < 8; j++)
            #pragma unroll
            for (int c = 0; c < 4; c++) acc[i][j][c] = 0.f;

    int r0 = tid >> 2;
    int cs0 = (tid & 3) * 8;
    const __nv_bfloat16* Ag  = g_featb + (size_t)(bmrow + r0) * 2048 + cs0;
    const __nv_bfloat16* Ag2 = Ag + (size_t)64 * 2048;
    const __nv_bfloat16* Bg  = g_wb   + (size_t)(bncol + r0) * 2048 + cs0;
    const __nv_bfloat16* Bg2 = Bg + (size_t)64 * 2048;

    uint4 pa0 = *(const uint4*)(Ag);
    uint4 pa1 = *(const uint4*)(Ag2);
    uint4 pb0 = *(const uint4*)(Bg);
    uint4 pb1 = *(const uint4*)(Bg2);

    const int KT = 2048 / BK;
    for (int kt = 0; kt < KT; kt++) {
        *(uint4*)&As[r0 * SSTR + cs0]        = pa0;
        *(uint4*)&As[(r0 + 64) * SSTR + cs0] = pa1;
        *(uint4*)&Bs[r0 * SSTR + cs0]        = pb0;
        *(uint4*)&Bs[(r0 + 64) * SSTR + cs0] = pb1;
        __syncthreads();
        if (kt + 1 < KT) {
            int kb = (kt + 1) * BK;
            pa0 = *(const uint4*)(Ag + kb);
            pa1 = *(const uint4*)(Ag2 + kb);
            pb0 = *(const uint4*)(Bg + kb);
            pb1 = *(const uint4*)(Bg2 + kb);
        }
        #pragma unroll
        for (int ks = 0; ks < BK; ks += 16) {
            uint32_t a[2][4], b[8][2];
            #pragma unroll
            for (int mt = 0; mt < 2; mt++) {
                int rr = (wm * 32 + mt * 16 + g) * SSTR + ks + q * 2;
                a[mt][0] = *(const uint32_t*)&As[rr];
                a[mt][1] = *(const uint32_t*)&As[rr + 8 * SSTR];
                a[mt][2] = *(const uint32_t*)&As[rr + 8];
                a[mt][3] = *(const uint32_t*)&As[rr + 8 * SSTR + 8];
            }
            #pragma unroll
            for (int nt = 0; nt < 8; nt++) {
                int rr = (wn * 64 + nt * 8 + g) * SSTR + ks + q * 2;
                b[nt][0] = *(const uint32_t*)&Bs[rr];
                b[nt][1] = *(const uint32_t*)&Bs[rr + 8];
            }
            #pragma unroll
            for (int mt = 0; mt < 2; mt++)
                #pragma unroll
                for (int nt = 0; nt < 8; nt++)
                    mma16816(acc[mt][nt], a[mt], b[nt]);
        }
        __syncthreads();
    }

    #pragma unroll
    for (int mt = 0; mt < 2; mt++) {
        int row = bmrow + wm * 32 + mt * 16 + g;
        float prow = 0.f, prow8 = 0.f;
        #pragma unroll
        for (int nt = 0; nt < 8; nt++) {
            int col = bncol + wn * 64 + nt * 8 + q * 2;
            float bb0 = b1[col], bb1 = b1[col + 1];
            float w20 = w2[col], w21 = w2[col + 1];
            float v0 = fmaxf(acc[mt][nt][0] + bb0, 0.f);
            float v1 = fmaxf(acc[mt][nt][1] + bb1, 0.f);
            float v2 = fmaxf(acc[mt][nt][2] + bb0, 0.f);
            float v3 = fmaxf(acc[mt][nt][3] + bb1, 0.f);
            prow  = fmaf(v0, w20, fmaf(v1, w21, prow));
            prow8 = fmaf(v2, w20, fmaf(v3, w21, prow8));
        }
        prow  += __shfl_xor_sync(0xffffffffu, prow, 1);
        prow  += __shfl_xor_sync(0xffffffffu, prow, 2);
        prow8 += __shfl_xor_sync(0xffffffffu, prow8, 1);
        prow8 += __shfl_xor_sync(0xffffffffu, prow8, 2);
        if (q == 0) {
            atomicAdd(&g_mixp[row], prow);
            atomicAdd(&g_mixp[row + 8], prow8);
        }
    }
}

// ---------------- k4: monolithic, 512 thr, fp16 e in 64KB smem, 2 CTAs/SM ---
// R3 architecture (row resident on-chip: single DRAM read + single write) with
// the phase-drain gap closed by co-residency: 2 CTAs/SM phase-offset so one
// CTA's write phase overlaps the other's read phase. Natural regs (512 thr;
// R4's failure was forced 32 regs at 1024 thr). fp16-e math R4-certified.
__global__ __launch_bounds__(512) void k4_out(const float* __restrict__ logits,
                                              const int* __restrict__ tok,
                                              const float* __restrict__ b2,
                                              float* __restrict__ out) {
    extern __shared__ __half eh[];         // VOC halves = 64000 B
    __shared__ float red[16];
    __shared__ float s_coef, s_mix;
    int n = blockIdx.x;
    int tid = threadIdx.x;
    int lane = tid & 31, warp = tid >> 5;
    const float* lrow = logits + (size_t)n * VOC;
    float* orow = out + (size_t)n * VOC;

    // phase A: read once from DRAM, e = exp(x) -> fp16 smem, accumulate sum
    float s = 0.f;
    #pragma unroll 4
    for (int i = tid * 4; i < VOC; i += 2048) {
        float4 x = __ldcg((const float4*)(lrow + i));
        float e0 = __expf(x.x), e1 = __expf(x.y);
        float e2 = __expf(x.z), e3 = __expf(x.w);
        s += (e0 + e1) + (e2 + e3);
        union { __half2 h2[2]; uint2 u; } pk;
        pk.h2[0] = __floats2half2_rn(e0, e1);
        pk.h2[1] = __floats2half2_rn(e2, e3);
        *(uint2*)&eh[i] = pk.u;
    }
    #pragma unroll
    for (int o = 16; o > 0; o >>= 1) s += __shfl_xor_sync(0xffffffffu, s, o);
    if (lane == 0) red[warp] = s;
    __syncthreads();
    if (tid == 0) {
        float t = 0.f;
        #pragma unroll
        for (int i = 0; i < 16; i++) t += red[i];
        float mix = 1.f / (1.f + expf(-(g_mixp[n] + b2[0])));
        s_mix = mix;
        s_coef = (1.f - mix) / t;
    }
    __syncthreads();
    float coef = s_coef;

    // phase B: out = log(coef*e + 1e-10) from smem-resident e, streaming store
    #pragma unroll 4
    for (int i = tid * 4; i < VOC; i += 2048) {
        union { __half2 h2[2]; uint2 u; } pk;
        pk.u = *(const uint2*)&eh[i];
        float2 e01 = __half22float2(pk.h2[0]);
        float2 e23 = __half22float2(pk.h2[1]);
        float4 o4;
        o4.x = __logf(fmaf(e01.x, coef, 1e-10f));
        o4.y = __logf(fmaf(e01.y, coef, 1e-10f));
        o4.z = __logf(fmaf(e23.x, coef, 1e-10f));
        o4.w = __logf(fmaf(e23.y, coef, 1e-10f));
        __stcs((float4*)(orow + i), o4);
    }
    __syncthreads();   // order row writes before the patch overwrites

    // patch the <=32 scattered tokens with the exact fp32 formula
    if (tid < KNN) {
        int t = tok[n * KNN + tid];
        float w = g_knnw[n * KNN + tid] * s_mix;
        unsigned grp = __match_any_sync(0xffffffffu, t);
        float tot = 0.f;
        #pragma unroll
        for (int j = 0; j < 32; j++)
            if (grp & (1u << j)) tot += __shfl_sync(0xffffffffu, w, j);
        if ((grp & ((1u << tid) - 1u)) == 0) {           // lowest lane of group
            float e = __expf(__ldcg(&lrow[t]));
            orow[t] = __logf(fmaf(e, coef, tot + 1e-10f));
        }
    }
}

#define K4_SMEM (VOC * (int)sizeof(__half))   // 64000 B -> 2 CTAs/SM

// ---------------- launch -----------------------------------------------------
extern "C" void kernel_launch(void* const* d_in, const int* in_sizes, int n_in,
                              void* d_out, int out_size) {
    const float* hidden = (const float*)d_in[0];
    const float* logits = (const float*)d_in[1];
    const float* dist   = (const float*)d_in[2];
    const int*   tok    = (const int*)d_in[3];
    const float* sh     = (const float*)d_in[4];
    const float* bw_w   = (const float*)d_in[5];
    const float* bw_b   = (const float*)d_in[6];
    const float* mw_w1  = (const float*)d_in[7];
    const float* mw_b1  = (const float*)d_in[8];
    const float* mw_w2  = (const float*)d_in[9];
    const float* mw_b2  = (const float*)d_in[10];
    float* out = (float*)d_out;

    cudaFuncSetAttribute(k4_out, cudaFuncAttributeMaxDynamicSharedMemorySize,
                         K4_SMEM);

    k0_convert_w<<<2048, 1024>>>(mw_w1);
    k1_ctx<<<N_ROWS, 256>>>(hidden, sh, dist, bw_w, bw_b);
    dim3 g2(DIM / BN, N_ROWS / BM);   // (8, 16)
    k2_gemm<<<g2, 256>>>(mw_b1, mw_w2);
    k4_out<<<N_ROWS, 512, K4_SMEM>>>(logits, tok, mw_b2, out);
}

// round 12
// speedup vs baseline: 2.0600x; 1.6443x over previous
#include <cuda_runtime.h>
#include <cuda_bf16.h>
#include <math_constants.h>
#include <cstdint>

#define N_ROWS 2048
#define DIM    1024
#define VOC    32000
#define KNN    32

// ---------------- scratch (static device globals: allocation-free) ----------
__device__ __nv_bfloat16 g_featb[(size_t)N_ROWS * 2048]; // [N, 2D] bf16
__device__ __nv_bfloat16 g_wb[(size_t)DIM * 2048];       // mw_w1 bf16
__device__ float g_knnw[N_ROWS * KNN];                   // softmax(-d/bw)
__device__ float g_mixp[N_ROWS];                         // partial mhid.w2 dots

// ---------------- k0: convert mw_w1 to bf16 + zero mixing partials ----------
__global__ void k0_convert_w(const float* __restrict__ w1) {
    int idx = blockIdx.x * blockDim.x + threadIdx.x;     // exactly DIM*2048
    g_wb[idx] = __float2bfloat16(w1[idx]);
    if (idx < N_ROWS) g_mixp[idx] = 0.f;
}

// ---------------- k1: ctx mean + feat(bf16) + bandwidth + knn softmax -------
__global__ __launch_bounds__(256) void k1_ctx(const float* __restrict__ hidden,
                       const float* __restrict__ sh,
                       const float* __restrict__ dist,
                       const float* __restrict__ bw_w,
                       const float* __restrict__ bw_b) {
    int n = blockIdx.x;
    int tid = threadIdx.x;                               // 256 threads
    int d = tid * 4;                                     // each thread: 4 dims
    const float* shrow = sh + (size_t)n * KNN * DIM;
    const float* hrow  = hidden + (size_t)n * DIM;

    float4 acc = make_float4(0.f, 0.f, 0.f, 0.f);
    #pragma unroll
    for (int k = 0; k < KNN; k++) {
        float4 v = *(const float4*)(shrow + k * DIM + d);
        acc.x += v.x; acc.y += v.y; acc.z += v.z; acc.w += v.w;
    }
    const float inv = 1.f / 32.f;
    float4 ctx = make_float4(acc.x * inv, acc.y * inv, acc.z * inv, acc.w * inv);
    float4 h = *(const float4*)(hrow + d);

    __nv_bfloat162* fb = (__nv_bfloat162*)&g_featb[(size_t)n * 2048 + d];
    fb[0] = __nv_bfloat162(__float2bfloat16(h.x), __float2bfloat16(h.y));
    fb[1] = __nv_bfloat162(__float2bfloat16(h.z), __float2bfloat16(h.w));
    __nv_bfloat162* fb2 = (__nv_bfloat162*)&g_featb[(size_t)n * 2048 + DIM + d];
    fb2[0] = __nv_bfloat162(__float2bfloat16(ctx.x), __float2bfloat16(ctx.y));
    fb2[1] = __nv_bfloat162(__float2bfloat16(ctx.z), __float2bfloat16(ctx.w));

    float4 w0 = *(const float4*)(bw_w + d);
    float4 w1 = *(const float4*)(bw_w + DIM + d);
    float bwacc = h.x * w0.x + h.y * w0.y + h.z * w0.z + h.w * w0.w
                + ctx.x * w1.x + ctx.y * w1.y + ctx.z * w1.z + ctx.w * w1.w;

    __shared__ float red[8];
    #pragma unroll
    for (int o = 16; o > 0; o >>= 1) bwacc += __shfl_xor_sync(0xffffffffu, bwacc, o);
    if ((tid & 31) == 0) red[tid >> 5] = bwacc;
    __syncthreads();
    __shared__ float s_bw;
    if (tid == 0) {
        float t = 0.f;
        #pragma unroll
        for (int i = 0; i < 8; i++) t += red[i];
        s_bw = expf(t + bw_b[0]);
    }
    __syncthreads();
    if (tid < 32) {
        float bw = s_bw;
        float t = -dist[n * KNN + tid] / bw;
        float m = t;
        #pragma unroll
        for (int o = 16; o > 0; o >>= 1) m = fmaxf(m, __shfl_xor_sync(0xffffffffu, m, o));
        float e = __expf(t - m);
        float ssum = e;
        #pragma unroll
        for (int o = 16; o > 0; o >>= 1) ssum += __shfl_xor_sync(0xffffffffu, ssum, o);
        g_knnw[n * KNN + tid] = e / ssum;
    }
}

// ---------------- k2: bf16 MMA GEMM, double-buffered smem, 1 sync/iter ------
#define BM 128
#define BN 128
#define BK 32
#define SSTR 40

__device__ __forceinline__ void mma16816(float c[4], const uint32_t a[4], const uint32_t b[2]) {
    asm volatile(
        "mma.sync.aligned.m16n8k16.row.col.f32.bf16.bf16.f32 "
        "{%0,%1,%2,%3}, {%4,%5,%6,%7}, {%8,%9}, {%0,%1,%2,%3};\n"
        : "+f"(c[0]), "+f"(c[1]), "+f"(c[2]), "+f"(c[3])
        : "r"(a[0]), "r"(a[1]), "r"(a[2]), "r"(a[3]), "r"(b[0]), "r"(b[1]));
}

__global__ __launch_bounds__(256) void k2_gemm(const float* __restrict__ b1,
                                               const float* __restrict__ w2) {
    __shared__ __nv_bfloat16 As[2][BM * SSTR];   // 2 x 10240 B
    __shared__ __nv_bfloat16 Bs[2][BN * SSTR];   // 2 x 10240 B
    int tid = threadIdx.x;
    int lane = tid & 31, warp = tid >> 5;
    int wm = warp >> 1, wn = warp & 1;
    int g = lane >> 2, q = lane & 3;
    int bmrow = blockIdx.y * BM;
    int bncol = blockIdx.x * BN;

    float acc[2][8][4];
    #pragma unroll
    for (int i = 0; i < 2; i++)
        #pragma unroll
        for (int j = 0; j < 8; j++)
            #pragma unroll
            for (int c = 0; c < 4; c++) acc[i][j][c] = 0.f;

    int r0 = tid >> 2;               // 0..63
    int cs0 = (tid & 3) * 8;         // 0,8,16,24 (bf16 elems)
    const __nv_bfloat16* Ag  = g_featb + (size_t)(bmrow + r0) * 2048 + cs0;
    const __nv_bfloat16* Ag2 = Ag + (size_t)64 * 2048;
    const __nv_bfloat16* Bg  = g_wb   + (size_t)(bncol + r0) * 2048 + cs0;
    const __nv_bfloat16* Bg2 = Bg + (size_t)64 * 2048;

    // preload tile 0 into buffer 0
    {
        uint4 a0 = *(const uint4*)(Ag);
        uint4 a1 = *(const uint4*)(Ag2);
        uint4 b0 = *(const uint4*)(Bg);
        uint4 b1v = *(const uint4*)(Bg2);
        *(uint4*)&As[0][r0 * SSTR + cs0]        = a0;
        *(uint4*)&As[0][(r0 + 64) * SSTR + cs0] = a1;
        *(uint4*)&Bs[0][r0 * SSTR + cs0]        = b0;
        *(uint4*)&Bs[0][(r0 + 64) * SSTR + cs0] = b1v;
    }
    __syncthreads();

    const int KT = 2048 / BK;        // 64
    for (int kt = 0; kt < KT; kt++) {
        int cur = kt & 1;
        uint4 pa0, pa1, pb0, pb1;
        if (kt + 1 < KT) {           // issue next tile's gmem loads early
            int kb = (kt + 1) * BK;
            pa0 = *(const uint4*)(Ag + kb);
            pa1 = *(const uint4*)(Ag2 + kb);
            pb0 = *(const uint4*)(Bg + kb);
            pb1 = *(const uint4*)(Bg2 + kb);
        }
        // compute on buffer `cur` (overlaps with loads above)
        #pragma unroll
        for (int ks = 0; ks < BK; ks += 16) {
            uint32_t a[2][4], b[8][2];
            #pragma unroll
            for (int mt = 0; mt < 2; mt++) {
                int rr = (wm * 32 + mt * 16 + g) * SSTR + ks + q * 2;
                a[mt][0] = *(const uint32_t*)&As[cur][rr];
                a[mt][1] = *(const uint32_t*)&As[cur][rr + 8 * SSTR];
                a[mt][2] = *(const uint32_t*)&As[cur][rr + 8];
                a[mt][3] = *(const uint32_t*)&As[cur][rr + 8 * SSTR + 8];
            }
            #pragma unroll
            for (int nt = 0; nt < 8; nt++) {
                int rr = (wn * 64 + nt * 8 + g) * SSTR + ks + q * 2;
                b[nt][0] = *(const uint32_t*)&Bs[cur][rr];
                b[nt][1] = *(const uint32_t*)&Bs[cur][rr + 8];
            }
            #pragma unroll
            for (int mt = 0; mt < 2; mt++)
                #pragma unroll
                for (int nt = 0; nt < 8; nt++)
                    mma16816(acc[mt][nt], a[mt], b[nt]);
        }
        // stage next tile into the other buffer (no conflict with readers of cur)
        if (kt + 1 < KT) {
            int nxt = cur ^ 1;
            *(uint4*)&As[nxt][r0 * SSTR + cs0]        = pa0;
            *(uint4*)&As[nxt][(r0 + 64) * SSTR + cs0] = pa1;
            *(uint4*)&Bs[nxt][r0 * SSTR + cs0]        = pb0;
            *(uint4*)&Bs[nxt][(r0 + 64) * SSTR + cs0] = pb1;
        }
        __syncthreads();             // single barrier per K-tile
    }

    // Epilogue: relu(acc + b1), dot with w2, accumulate per-row mixing partials.
    #pragma unroll
    for (int mt = 0; mt < 2; mt++) {
        int row = bmrow + wm * 32 + mt * 16 + g;
        float prow = 0.f, prow8 = 0.f;
        #pragma unroll
        for (int nt = 0; nt < 8; nt++) {
            int col = bncol + wn * 64 + nt * 8 + q * 2;
            float bb0 = b1[col], bb1 = b1[col + 1];
            float w20 = w2[col], w21 = w2[col + 1];
            float v0 = fmaxf(acc[mt][nt][0] + bb0, 0.f);
            float v1 = fmaxf(acc[mt][nt][1] + bb1, 0.f);
            float v2 = fmaxf(acc[mt][nt][2] + bb0, 0.f);
            float v3 = fmaxf(acc[mt][nt][3] + bb1, 0.f);
            prow  = fmaf(v0, w20, fmaf(v1, w21, prow));
            prow8 = fmaf(v2, w20, fmaf(v3, w21, prow8));
        }
        prow  += __shfl_xor_sync(0xffffffffu, prow, 1);
        prow  += __shfl_xor_sync(0xffffffffu, prow, 2);
        prow8 += __shfl_xor_sync(0xffffffffu, prow8, 1);
        prow8 += __shfl_xor_sync(0xffffffffu, prow8, 2);
        if (q == 0) {
            atomicAdd(&g_mixp[row], prow);
            atomicAdd(&g_mixp[row + 8], prow8);
        }
    }
}

// ---------------- k4: R3-exact (best measured: 157.9us) ---------------------
// 3 phases, fp32 smem (1 CTA/SM, 32 warps), in-smem fp32 atomic scatter.
__global__ __launch_bounds__(1024) void k4_out(const float* __restrict__ logits,
                                               const int* __restrict__ tok,
                                               const float* __restrict__ b2,
                                               float* __restrict__ out) {
    extern __shared__ float sm[];          // VOC floats = 128000 B
    __shared__ float redm[32], reds[32];
    int n = blockIdx.x;
    int tid = threadIdx.x;
    int lane = tid & 31, warp = tid >> 5;
    const float* lrow = logits + (size_t)n * VOC;

    float m = -CUDART_INF_F, s = 0.f;
    for (int i = tid; i < VOC; i += 1024) {
        float x = lrow[i];
        sm[i] = x;
        float mn = fmaxf(m, x);
        s = s * __expf(m - mn) + __expf(x - mn);
        m = mn;
    }
    #pragma unroll
    for (int o = 16; o > 0; o >>= 1) {
        float m2 = __shfl_xor_sync(0xffffffffu, m, o);
        float s2 = __shfl_xor_sync(0xffffffffu, s, o);
        float mn = fmaxf(m, m2);
        s = s * __expf(m - mn) + s2 * __expf(m2 - mn);
        m = mn;
    }
    if (lane == 0) { redm[warp] = m; reds[warp] = s; }
    __syncthreads();
    if (warp == 0) {
        m = redm[lane]; s = reds[lane];
        #pragma unroll
        for (int o = 16; o > 0; o >>= 1) {
            float m2 = __shfl_xor_sync(0xffffffffu, m, o);
            float s2 = __shfl_xor_sync(0xffffffffu, s, o);
            float mn = fmaxf(m, m2);
            s = s * __expf(m - mn) + s2 * __expf(m2 - mn);
            m = mn;
        }
        if (lane == 0) { redm[0] = m; reds[0] = s; }
    }
    __syncthreads();
    float M = redm[0];
    float mix = 1.f / (1.f + expf(-(g_mixp[n] + b2[0])));
    float coef = (1.f - mix) / reds[0];
    for (int i = tid; i < VOC; i += 1024)
        sm[i] = coef * __expf(sm[i] - M);
    __syncthreads();
    if (tid < KNN) {
        float w = g_knnw[n * KNN + tid] * mix;
        atomicAdd(&sm[tok[n * KNN + tid]], w);   // duplicates accumulate
    }
    __syncthreads();
    float* orow = out + (size_t)n * VOC;
    for (int i = tid; i < VOC; i += 1024)
        orow[i] = __logf(sm[i] + 1e-10f);
}

// ---------------- launch -----------------------------------------------------
extern "C" void kernel_launch(void* const* d_in, const int* in_sizes, int n_in,
                              void* d_out, int out_size) {
    const float* hidden = (const float*)d_in[0];
    const float* logits = (const float*)d_in[1];
    const float* dist   = (const float*)d_in[2];
    const int*   tok    = (const int*)d_in[3];
    const float* sh     = (const float*)d_in[4];
    const float* bw_w   = (const float*)d_in[5];
    const float* bw_b   = (const float*)d_in[6];
    const float* mw_w1  = (const float*)d_in[7];
    const float* mw_b1  = (const float*)d_in[8];
    const float* mw_w2  = (const float*)d_in[9];
    const float* mw_b2  = (const float*)d_in[10];
    float* out = (float*)d_out;

    cudaFuncSetAttribute(k4_out, cudaFuncAttributeMaxDynamicSharedMemorySize,
                         VOC * (int)sizeof(float));

    k0_convert_w<<<2048, 1024>>>(mw_w1);
    k1_ctx<<<N_ROWS, 256>>>(hidden, sh, dist, bw_w, bw_b);
    dim3 g2(DIM / BN, N_ROWS / BM);   // (8, 16)
    k2_gemm<<<g2, 256>>>(mw_b1, mw_w2);
    k4_out<<<N_ROWS, 1024, VOC * sizeof(float)>>>(logits, tok, mw_b2, out);
}

// round 13
// speedup vs baseline: 2.2718x; 1.1029x over previous
#include <cuda_runtime.h>
#include <cuda_bf16.h>
#include <math_constants.h>
#include <cstdint>

#define N_ROWS 2048
#define DIM    1024
#define VOC    32000
#define KNN    32

// ---------------- scratch (static device globals: allocation-free) ----------
__device__ __nv_bfloat16 g_featb[(size_t)N_ROWS * 2048]; // [N, 2D] bf16
__device__ __nv_bfloat16 g_wb[(size_t)DIM * 2048];       // mw_w1 bf16
__device__ float g_knnw[N_ROWS * KNN];                   // softmax(-d/bw)
__device__ float g_mixp[N_ROWS];                         // partial mhid.w2 dots

// ---------------- k0: convert mw_w1 to bf16 + zero mixing partials ----------
__global__ void k0_convert_w(const float* __restrict__ w1) {
    int idx = blockIdx.x * blockDim.x + threadIdx.x;     // exactly DIM*2048
    g_wb[idx] = __float2bfloat16(w1[idx]);
    if (idx < N_ROWS) g_mixp[idx] = 0.f;
}

// ---------------- k1: ctx mean + feat(bf16) + bandwidth + knn softmax -------
__global__ __launch_bounds__(256) void k1_ctx(const float* __restrict__ hidden,
                       const float* __restrict__ sh,
                       const float* __restrict__ dist,
                       const float* __restrict__ bw_w,
                       const float* __restrict__ bw_b) {
    int n = blockIdx.x;
    int tid = threadIdx.x;                               // 256 threads
    int d = tid * 4;                                     // each thread: 4 dims
    const float* shrow = sh + (size_t)n * KNN * DIM;
    const float* hrow  = hidden + (size_t)n * DIM;

    float4 acc = make_float4(0.f, 0.f, 0.f, 0.f);
    #pragma unroll
    for (int k = 0; k < KNN; k++) {
        float4 v = *(const float4*)(shrow + k * DIM + d);
        acc.x += v.x; acc.y += v.y; acc.z += v.z; acc.w += v.w;
    }
    const float inv = 1.f / 32.f;
    float4 ctx = make_float4(acc.x * inv, acc.y * inv, acc.z * inv, acc.w * inv);
    float4 h = *(const float4*)(hrow + d);

    __nv_bfloat162* fb = (__nv_bfloat162*)&g_featb[(size_t)n * 2048 + d];
    fb[0] = __nv_bfloat162(__float2bfloat16(h.x), __float2bfloat16(h.y));
    fb[1] = __nv_bfloat162(__float2bfloat16(h.z), __float2bfloat16(h.w));
    __nv_bfloat162* fb2 = (__nv_bfloat162*)&g_featb[(size_t)n * 2048 + DIM + d];
    fb2[0] = __nv_bfloat162(__float2bfloat16(ctx.x), __float2bfloat16(ctx.y));
    fb2[1] = __nv_bfloat162(__float2bfloat16(ctx.z), __float2bfloat16(ctx.w));

    float4 w0 = *(const float4*)(bw_w + d);
    float4 w1 = *(const float4*)(bw_w + DIM + d);
    float bwacc = h.x * w0.x + h.y * w0.y + h.z * w0.z + h.w * w0.w
                + ctx.x * w1.x + ctx.y * w1.y + ctx.z * w1.z + ctx.w * w1.w;

    __shared__ float red[8];
    #pragma unroll
    for (int o = 16; o > 0; o >>= 1) bwacc += __shfl_xor_sync(0xffffffffu, bwacc, o);
    if ((tid & 31) == 0) red[tid >> 5] = bwacc;
    __syncthreads();
    __shared__ float s_bw;
    if (tid == 0) {
        float t = 0.f;
        #pragma unroll
        for (int i = 0; i < 8; i++) t += red[i];
        s_bw = expf(t + bw_b[0]);
    }
    __syncthreads();
    if (tid < 32) {
        float bw = s_bw;
        float t = -dist[n * KNN + tid] / bw;
        float m = t;
        #pragma unroll
        for (int o = 16; o > 0; o >>= 1) m = fmaxf(m, __shfl_xor_sync(0xffffffffu, m, o));
        float e = __expf(t - m);
        float ssum = e;
        #pragma unroll
        for (int o = 16; o > 0; o >>= 1) ssum += __shfl_xor_sync(0xffffffffu, ssum, o);
        g_knnw[n * KNN + tid] = e / ssum;
    }
}

// ---------------- k2: bf16 MMA GEMM, double-buffered smem, 1 sync/iter ------
#define BM 128
#define BN 128
#define BK 32
#define SSTR 40

__device__ __forceinline__ void mma16816(float c[4], const uint32_t a[4], const uint32_t b[2]) {
    asm volatile(
        "mma.sync.aligned.m16n8k16.row.col.f32.bf16.bf16.f32 "
        "{%0,%1,%2,%3}, {%4,%5,%6,%7}, {%8,%9}, {%0,%1,%2,%3};\n"
        : "+f"(c[0]), "+f"(c[1]), "+f"(c[2]), "+f"(c[3])
        : "r"(a[0]), "r"(a[1]), "r"(a[2]), "r"(a[3]), "r"(b[0]), "r"(b[1]));
}

__global__ __launch_bounds__(256) void k2_gemm(const float* __restrict__ b1,
                                               const float* __restrict__ w2) {
    __shared__ __nv_bfloat16 As[2][BM * SSTR];   // 2 x 10240 B
    __shared__ __nv_bfloat16 Bs[2][BN * SSTR];   // 2 x 10240 B
    int tid = threadIdx.x;
    int lane = tid & 31, warp = tid >> 5;
    int wm = warp >> 1, wn = warp & 1;
    int g = lane >> 2, q = lane & 3;
    int bmrow = blockIdx.y * BM;
    int bncol = blockIdx.x * BN;

    float acc[2][8][4];
    #pragma unroll
    for (int i = 0; i < 2; i++)
        #pragma unroll
        for (int j = 0; j < 8; j++)
            #pragma unroll
            for (int c = 0; c < 4; c++) acc[i][j][c] = 0.f;

    int r0 = tid >> 2;               // 0..63
    int cs0 = (tid & 3) * 8;         // 0,8,16,24 (bf16 elems)
    const __nv_bfloat16* Ag  = g_featb + (size_t)(bmrow + r0) * 2048 + cs0;
    const __nv_bfloat16* Ag2 = Ag + (size_t)64 * 2048;
    const __nv_bfloat16* Bg  = g_wb   + (size_t)(bncol + r0) * 2048 + cs0;
    const __nv_bfloat16* Bg2 = Bg + (size_t)64 * 2048;

    // preload tile 0 into buffer 0
    {
        uint4 a0 = *(const uint4*)(Ag);
        uint4 a1 = *(const uint4*)(Ag2);
        uint4 b0 = *(const uint4*)(Bg);
        uint4 b1v = *(const uint4*)(Bg2);
        *(uint4*)&As[0][r0 * SSTR + cs0]        = a0;
        *(uint4*)&As[0][(r0 + 64) * SSTR + cs0] = a1;
        *(uint4*)&Bs[0][r0 * SSTR + cs0]        = b0;
        *(uint4*)&Bs[0][(r0 + 64) * SSTR + cs0] = b1v;
    }
    __syncthreads();

    const int KT = 2048 / BK;        // 64
    for (int kt = 0; kt < KT; kt++) {
        int cur = kt & 1;
        uint4 pa0, pa1, pb0, pb1;
        if (kt + 1 < KT) {           // issue next tile's gmem loads early
            int kb = (kt + 1) * BK;
            pa0 = *(const uint4*)(Ag + kb);
            pa1 = *(const uint4*)(Ag2 + kb);
            pb0 = *(const uint4*)(Bg + kb);
            pb1 = *(const uint4*)(Bg2 + kb);
        }
        // compute on buffer `cur` (overlaps with loads above)
        #pragma unroll
        for (int ks = 0; ks < BK; ks += 16) {
            uint32_t a[2][4], b[8][2];
            #pragma unroll
            for (int mt = 0; mt < 2; mt++) {
                int rr = (wm * 32 + mt * 16 + g) * SSTR + ks + q * 2;
                a[mt][0] = *(const uint32_t*)&As[cur][rr];
                a[mt][1] = *(const uint32_t*)&As[cur][rr + 8 * SSTR];
                a[mt][2] = *(const uint32_t*)&As[cur][rr + 8];
                a[mt][3] = *(const uint32_t*)&As[cur][rr + 8 * SSTR + 8];
            }
            #pragma unroll
            for (int nt = 0; nt < 8; nt++) {
                int rr = (wn * 64 + nt * 8 + g) * SSTR + ks + q * 2;
                b[nt][0] = *(const uint32_t*)&Bs[cur][rr];
                b[nt][1] = *(const uint32_t*)&Bs[cur][rr + 8];
            }
            #pragma unroll
            for (int mt = 0; mt < 2; mt++)
                #pragma unroll
                for (int nt = 0; nt < 8; nt++)
                    mma16816(acc[mt][nt], a[mt], b[nt]);
        }
        // stage next tile into the other buffer (no conflict with readers of cur)
        if (kt + 1 < KT) {
            int nxt = cur ^ 1;
            *(uint4*)&As[nxt][r0 * SSTR + cs0]        = pa0;
            *(uint4*)&As[nxt][(r0 + 64) * SSTR + cs0] = pa1;
            *(uint4*)&Bs[nxt][r0 * SSTR + cs0]        = pb0;
            *(uint4*)&Bs[nxt][(r0 + 64) * SSTR + cs0] = pb1;
        }
        __syncthreads();             // single barrier per K-tile
    }

    // Epilogue: relu(acc + b1), dot with w2, accumulate per-row mixing partials.
    #pragma unroll
    for (int mt = 0; mt < 2; mt++) {
        int row = bmrow + wm * 32 + mt * 16 + g;
        float prow = 0.f, prow8 = 0.f;
        #pragma unroll
        for (int nt = 0; nt < 8; nt++) {
            int col = bncol + wn * 64 + nt * 8 + q * 2;
            float bb0 = b1[col], bb1 = b1[col + 1];
            float w20 = w2[col], w21 = w2[col + 1];
            float v0 = fmaxf(acc[mt][nt][0] + bb0, 0.f);
            float v1 = fmaxf(acc[mt][nt][1] + bb1, 0.f);
            float v2 = fmaxf(acc[mt][nt][2] + bb0, 0.f);
            float v3 = fmaxf(acc[mt][nt][3] + bb1, 0.f);
            prow  = fmaf(v0, w20, fmaf(v1, w21, prow));
            prow8 = fmaf(v2, w20, fmaf(v3, w21, prow8));
        }
        prow  += __shfl_xor_sync(0xffffffffu, prow, 1);
        prow  += __shfl_xor_sync(0xffffffffu, prow, 2);
        prow8 += __shfl_xor_sync(0xffffffffu, prow8, 1);
        prow8 += __shfl_xor_sync(0xffffffffu, prow8, 2);
        if (q == 0) {
            atomicAdd(&g_mixp[row], prow);
            atomicAdd(&g_mixp[row + 8], prow8);
        }
    }
}

// ---------------- k4: R3-exact vectorized 3-phase (measured 157.9us) --------
// pass1: float4 ldcg + max only (no MUFU in dep chain); pass2: exp+sum over
// smem; exp-domain scatter; pass3: log + streaming store.
__global__ __launch_bounds__(1024) void k4_out(const float* __restrict__ logits,
                                               const int* __restrict__ tok,
                                               const float* __restrict__ b2,
                                               float* __restrict__ out) {
    extern __shared__ float sm[];          // VOC floats = 128000 B
    __shared__ float red[32];
    __shared__ float s_M, s_coef, s_mix;
    int n = blockIdx.x;
    int tid = threadIdx.x;
    int lane = tid & 31, warp = tid >> 5;
    const float* lrow = logits + (size_t)n * VOC;

    // pass 1: load (float4, L2-cached) + running max
    float m = -CUDART_INF_F;
    #pragma unroll 8
    for (int i = tid * 4; i < VOC; i += 4096) {
        float4 x = __ldcg((const float4*)(lrow + i));
        *(float4*)&sm[i] = x;
        m = fmaxf(m, fmaxf(fmaxf(x.x, x.y), fmaxf(x.z, x.w)));
    }
    #pragma unroll
    for (int o = 16; o > 0; o >>= 1) m = fmaxf(m, __shfl_xor_sync(0xffffffffu, m, o));
    if (lane == 0) red[warp] = m;
    __syncthreads();
    if (warp == 0) {
        m = red[lane];
        #pragma unroll
        for (int o = 16; o > 0; o >>= 1) m = fmaxf(m, __shfl_xor_sync(0xffffffffu, m, o));
        if (lane == 0) s_M = m;
    }
    __syncthreads();
    float M = s_M;

    // pass 2: e = exp(x - M) into smem, accumulate sum
    float s = 0.f;
    #pragma unroll 8
    for (int i = tid * 4; i < VOC; i += 4096) {
        float4 x = *(float4*)&sm[i];
        float4 e;
        e.x = __expf(x.x - M); e.y = __expf(x.y - M);
        e.z = __expf(x.z - M); e.w = __expf(x.w - M);
        *(float4*)&sm[i] = e;
        s += (e.x + e.y) + (e.z + e.w);
    }
    #pragma unroll
    for (int o = 16; o > 0; o >>= 1) s += __shfl_xor_sync(0xffffffffu, s, o);
    if (lane == 0) red[warp] = s;
    __syncthreads();
    if (warp == 0) {
        s = red[lane];
        #pragma unroll
        for (int o = 16; o > 0; o >>= 1) s += __shfl_xor_sync(0xffffffffu, s, o);
        if (lane == 0) {
            float mix = 1.f / (1.f + expf(-(g_mixp[n] + b2[0])));
            s_mix = mix;
            s_coef = (1.f - mix) / s;   // prob = coef * e
        }
    }
    __syncthreads();
    float coef = s_coef;

    // sparse scatter in exp-domain: coef*(e + w/coef) = (1-mix)p + mix*knnw
    if (tid < KNN) {
        float w = g_knnw[n * KNN + tid] * s_mix;
        atomicAdd(&sm[tok[n * KNN + tid]], w / coef);
    }
    __syncthreads();

    // pass 3: log + streaming store
    float* orow = out + (size_t)n * VOC;
    #pragma unroll 8
    for (int i = tid * 4; i < VOC; i += 4096) {
        float4 e = *(float4*)&sm[i];
        float4 o4;
        o4.x = __logf(fmaf(e.x, coef, 1e-10f));
        o4.y = __logf(fmaf(e.y, coef, 1e-10f));
        o4.z = __logf(fmaf(e.z, coef, 1e-10f));
        o4.w = __logf(fmaf(e.w, coef, 1e-10f));
        __stcs((float4*)(orow + i), o4);
    }
}

// ---------------- launch -----------------------------------------------------
extern "C" void kernel_launch(void* const* d_in, const int* in_sizes, int n_in,
                              void* d_out, int out_size) {
    const float* hidden = (const float*)d_in[0];
    const float* logits = (const float*)d_in[1];
    const float* dist   = (const float*)d_in[2];
    const int*   tok    = (const int*)d_in[3];
    const float* sh     = (const float*)d_in[4];
    const float* bw_w   = (const float*)d_in[5];
    const float* bw_b   = (const float*)d_in[6];
    const float* mw_w1  = (const float*)d_in[7];
    const float* mw_b1  = (const float*)d_in[8];
    const float* mw_w2  = (const float*)d_in[9];
    const float* mw_b2  = (const float*)d_in[10];
    float* out = (float*)d_out;

    cudaFuncSetAttribute(k4_out, cudaFuncAttributeMaxDynamicSharedMemorySize,
                         VOC * (int)sizeof(float));

    k0_convert_w<<<2048, 1024>>>(mw_w1);
    k1_ctx<<<N_ROWS, 256>>>(hidden, sh, dist, bw_w, bw_b);
    dim3 g2(DIM / BN, N_ROWS / BM);   // (8, 16)
    k2_gemm<<<g2, 256>>>(mw_b1, mw_w2);
    k4_out<<<N_ROWS, 1024, VOC * sizeof(float)>>>(logits, tok, mw_b2, out);
}